// round 15
// baseline (speedup 1.0000x reference)
#include <cuda_runtime.h>
#include <cuda_fp16.h>
#include <cstdint>
#include <cstddef>

#define NTOK   1024
#define BATCH  32
#define HEADS  8
#define DHEAD  64
#define INNER  512
#define QKV3   (3*INNER)
#define MROWS  (BATCH*NTOK)
#define BK     32

#define LOG2E  1.44269504f
#define QSCALE (0.125f * LOG2E)
#define EXP2_OFF 5.7707801f    // 4 * log2(e): P = 2^(S2+bias2-OFF) = e^(S+bias-4)

// ---------------- scratch (static device globals; no allocation allowed) ----
__device__ __half g_biasb[(size_t)HEADS*NTOK*NTOK];   // bias * log2e (fp16)

__device__ __half g_x_hi [(size_t)MROWS*INNER];       // x 2-term (A-side of qkv)
__device__ __half g_x_lo [(size_t)MROWS*INNER];
__device__ __half g_att  [(size_t)MROWS*INNER];       // attention out, single fp16
__device__ __half g_wqkvT[(size_t)QKV3*INNER];        // single fp16 (B-side)
__device__ __half g_woutT[(size_t)INNER*INNER];       // single fp16 (B-side)

// attention operands (all single fp16): Q,K [b,h,n,64]; V transposed [b,h,64,n]
__device__ __half g_q [(size_t)BATCH*HEADS*NTOK*DHEAD];  // Q pre-scaled by 0.125*log2e
__device__ __half g_k [(size_t)BATCH*HEADS*NTOK*DHEAD];
__device__ __half g_vT[(size_t)BATCH*HEADS*DHEAD*NTOK];

// ---------------- PTX helpers (base sm_103-safe) ----------------------------
__device__ __forceinline__ uint32_t smem_u32(const void* p) {
    uint32_t a;
    asm("{ .reg .u64 t; cvta.to.shared.u64 t, %1; cvt.u32.u64 %0, t; }"
        : "=r"(a) : "l"(p));
    return a;
}
__device__ __forceinline__ void cp16(uint32_t dst, const void* src) {
    asm volatile("cp.async.cg.shared.global [%0], [%1], 16;"
                 :: "r"(dst), "l"(src) : "memory");
}
#define CP_COMMIT() asm volatile("cp.async.commit_group;" ::: "memory")
#define CP_WAIT1()  asm volatile("cp.async.wait_group 1;" ::: "memory")
#define CP_WAIT0()  asm volatile("cp.async.wait_group 0;" ::: "memory")

#define LDSM4(r0, r1, r2, r3, addr)                                            \
    asm volatile("ldmatrix.sync.aligned.m8n8.x4.shared.b16 {%0,%1,%2,%3}, [%4];" \
                 : "=r"(r0), "=r"(r1), "=r"(r2), "=r"(r3) : "r"(addr))

#define MMA16816(d, a, b)                                                      \
    asm volatile("mma.sync.aligned.m16n8k16.row.col.f32.f16.f16.f32 "          \
                 "{%0,%1,%2,%3}, {%4,%5,%6,%7}, {%8,%9}, {%0,%1,%2,%3};"       \
                 : "+f"((d)[0]), "+f"((d)[1]), "+f"((d)[2]), "+f"((d)[3])      \
                 : "r"((a)[0]), "r"((a)[1]), "r"((a)[2]), "r"((a)[3]),         \
                   "r"((b)[0]), "r"((b)[1]))

__device__ __forceinline__ float ex2(float x) {
    float r;
    asm("ex2.approx.f32 %0, %1;" : "=f"(r) : "f"(x));
    return r;
}

__device__ __forceinline__ void split2h(float a, float b, uint32_t& hi, uint32_t& lo) {
    __half ha = __float2half_rn(a), hb = __float2half_rn(b);
    float ra = a - __half2float(ha), rb = b - __half2float(hb);
    __half la = __float2half_rn(ra), lb = __float2half_rn(rb);
    hi = ((uint32_t)__half_as_ushort(hb) << 16) | __half_as_ushort(ha);
    lo = ((uint32_t)__half_as_ushort(lb) << 16) | __half_as_ushort(la);
}
__device__ __forceinline__ uint32_t pack2h(float a, float b) {
    __half2 h = __float22half2_rn(make_float2(a, b));
    return *(uint32_t*)&h;
}

// ---------------------------------------------------------------------------
// bias (fp16), pre-scaled by log2(e) for the exp2-domain softmax
// ---------------------------------------------------------------------------
__global__ void bias_kernel(const float* __restrict__ bias_table,
                            const int*   __restrict__ rel_index) {
    int idx = blockIdx.x * blockDim.x + threadIdx.x;
    if (idx >= NTOK * NTOK) return;
    int r = rel_index[idx];
#pragma unroll
    for (int h = 0; h < HEADS; h++)
        g_biasb[(size_t)h * NTOK * NTOK + idx] =
            __float2half_rn(bias_table[r * HEADS + h] * LOG2E);
}

// ---------------------------------------------------------------------------
// split fp32 -> (hi, lo) fp16, same layout.
// ---------------------------------------------------------------------------
__global__ void split_kernel(const float* __restrict__ in,
                             __half* __restrict__ hi,
                             __half* __restrict__ lo, size_t n4) {
    size_t i = (size_t)blockIdx.x * blockDim.x + threadIdx.x;
    if (i >= n4) return;
    float4 v = ((const float4*)in)[i];
    uint32_t hp[2], lp[2];
    split2h(v.x, v.y, hp[0], lp[0]);
    split2h(v.z, v.w, hp[1], lp[1]);
    ((uint2*)hi)[i] = make_uint2(hp[0], hp[1]);
    ((uint2*)lo)[i] = make_uint2(lp[0], lp[1]);
}

// transpose weights: in [K,N] fp32 -> single fp16 [N,K]
__global__ void splitTh_kernel(const float* __restrict__ in,
                               __half* __restrict__ hT, int K, int N) {
    int idx = blockIdx.x * blockDim.x + threadIdx.x;
    if (idx >= K * N) return;
    int n = idx / K, k = idx - n * K;
    hT[idx] = __float2half_rn(in[(size_t)k * N + n]);
}

// ---------------------------------------------------------------------------
// GEMM mainloop, A 2-term: (Ahi+Alo) @ B^T, K=512, 3-stage cp.async.
// ---------------------------------------------------------------------------
#define STAGE2_BYTES 24576
#define GSMEM2_BYTES (3 * STAGE2_BYTES)

__device__ __forceinline__ void gemm_mainloop2(
    const __half* srcAh, const __half* srcAl, const __half* srcB,
    uint32_t sb, int tid, int wm, int wn, int lane, float acc[4][4][4]) {
    constexpr int K = 512;

    auto issue = [&](int stage, int c) {
        const uint32_t d0 = sb + stage * STAGE2_BYTES;
        const int k0 = c * BK;
        const __half* srcs[3] = {srcAh, srcAl, srcB};
#pragma unroll
        for (int o = 0; o < 3; o++) {
#pragma unroll
            for (int i = 0; i < 2; i++) {
                int cid = tid + 256 * i;
                int row = cid >> 2, ch = cid & 3;
                int cc = ch ^ ((row >> 1) & 3);
                cp16(d0 + o * 8192 + row * 64 + cc * 16,
                     srcs[o] + (size_t)row * K + k0 + ch * 8);
            }
        }
    };

    issue(0, 0); CP_COMMIT();
    issue(1, 1); CP_COMMIT();

    for (int c = 0; c < K / BK; c++) {
        const int s = c % 3;
        CP_WAIT1();
        __syncthreads();
        if (c + 2 < K / BK) issue((c + 2) % 3, c + 2);
        CP_COMMIT();

        const uint32_t stg = sb + s * STAGE2_BYTES;
#pragma unroll
        for (int ks = 0; ks < 2; ks++) {
            uint32_t aH[4][4], aL[4][4], bF[4][2];
#pragma unroll
            for (int mt = 0; mt < 4; mt++) {
                int row = wm * 64 + mt * 16 + (lane & 15);
                int ch = 2 * ks + (lane >> 4);
                int cc = ch ^ ((row >> 1) & 3);
                uint32_t ad = stg + row * 64 + cc * 16;
                LDSM4(aH[mt][0], aH[mt][1], aH[mt][2], aH[mt][3], ad);
                LDSM4(aL[mt][0], aL[mt][1], aL[mt][2], aL[mt][3], ad + 8192);
            }
#pragma unroll
            for (int np = 0; np < 2; np++) {
                int rown = wn * 32 + np * 16 + (lane & 7) + ((lane >> 4) << 3);
                int ch = 2 * ks + ((lane >> 3) & 1);
                int cc = ch ^ ((rown >> 1) & 3);
                uint32_t bd = stg + 16384 + rown * 64 + cc * 16;
                LDSM4(bF[2*np][0], bF[2*np][1], bF[2*np+1][0], bF[2*np+1][1], bd);
            }
#pragma unroll
            for (int mt = 0; mt < 4; mt++)
#pragma unroll
                for (int nt = 0; nt < 4; nt++) {
                    MMA16816(acc[mt][nt], aH[mt], bF[nt]);
                    MMA16816(acc[mt][nt], aL[mt], bF[nt]);
                }
        }
    }
}

// ---------------------------------------------------------------------------
// GEMM mainloop, A single-term: A @ B^T, K=512, 3-stage cp.async.
// ---------------------------------------------------------------------------
#define STAGE1_BYTES 16384
#define GSMEM1_BYTES (3 * STAGE1_BYTES)

__device__ __forceinline__ void gemm_mainloop1(
    const __half* srcA, const __half* srcB,
    uint32_t sb, int tid, int wm, int wn, int lane, float acc[4][4][4]) {
    constexpr int K = 512;

    auto issue = [&](int stage, int c) {
        const uint32_t d0 = sb + stage * STAGE1_BYTES;
        const int k0 = c * BK;
        const __half* srcs[2] = {srcA, srcB};
#pragma unroll
        for (int o = 0; o < 2; o++) {
#pragma unroll
            for (int i = 0; i < 2; i++) {
                int cid = tid + 256 * i;
                int row = cid >> 2, ch = cid & 3;
                int cc = ch ^ ((row >> 1) & 3);
                cp16(d0 + o * 8192 + row * 64 + cc * 16,
                     srcs[o] + (size_t)row * K + k0 + ch * 8);
            }
        }
    };

    issue(0, 0); CP_COMMIT();
    issue(1, 1); CP_COMMIT();

    for (int c = 0; c < K / BK; c++) {
        const int s = c % 3;
        CP_WAIT1();
        __syncthreads();
        if (c + 2 < K / BK) issue((c + 2) % 3, c + 2);
        CP_COMMIT();

        const uint32_t stg = sb + s * STAGE1_BYTES;
#pragma unroll
        for (int ks = 0; ks < 2; ks++) {
            uint32_t aF[4][4], bF[4][2];
#pragma unroll
            for (int mt = 0; mt < 4; mt++) {
                int row = wm * 64 + mt * 16 + (lane & 15);
                int ch = 2 * ks + (lane >> 4);
                int cc = ch ^ ((row >> 1) & 3);
                LDSM4(aF[mt][0], aF[mt][1], aF[mt][2], aF[mt][3],
                      stg + row * 64 + cc * 16);
            }
#pragma unroll
            for (int np = 0; np < 2; np++) {
                int rown = wn * 32 + np * 16 + (lane & 7) + ((lane >> 4) << 3);
                int ch = 2 * ks + ((lane >> 3) & 1);
                int cc = ch ^ ((rown >> 1) & 3);
                uint32_t bd = stg + 8192 + rown * 64 + cc * 16;
                LDSM4(bF[2*np][0], bF[2*np][1], bF[2*np+1][0], bF[2*np+1][1], bd);
            }
#pragma unroll
            for (int mt = 0; mt < 4; mt++)
#pragma unroll
                for (int nt = 0; nt < 4; nt++)
                    MMA16816(acc[mt][nt], aF[mt], bF[nt]);
        }
    }
}

// ---------------------------------------------------------------------------
// QKV GEMM with fused repack epilogue + section-wise precision:
//   Q (sec 0): x 2-term mainloop, scale 0.125*log2e -> g_q [bh,tok,64]
//   K (sec 1): x single-term mainloop               -> g_k [bh,tok,64]
//   V (sec 2): x single-term mainloop + transpose   -> g_vT [bh,d,tok]
// ---------------------------------------------------------------------------
__global__ __launch_bounds__(256, 2)
void gemm_qkv() {
    extern __shared__ char smem[];
    const int tid = threadIdx.x, wid = tid >> 5, lane = tid & 31;
    const int wm = wid >> 2, wn = wid & 3;
    const int bm = blockIdx.y * 128;
    const int sec = blockIdx.x >> 2;        // 0=Q 1=K 2=V
    const int cb  = blockIdx.x & 3;
    const uint32_t sb = smem_u32(smem);

    constexpr int K = 512;
    float acc[4][4][4] = {};
    if (sec == 0) {
        gemm_mainloop2(g_x_hi + (size_t)bm * K, g_x_lo + (size_t)bm * K,
                       g_wqkvT + (size_t)(cb * 128) * K,
                       sb, tid, wm, wn, lane, acc);
    } else {
        gemm_mainloop1(g_x_hi + (size_t)bm * K,
                       g_wqkvT + (size_t)(sec * 512 + cb * 128) * K,
                       sb, tid, wm, wn, lane, acc);
    }

    const int b = bm >> 10, tokb = bm & 1023;

    if (sec < 2) {
        __half* oq = sec ? g_k : g_q;
        const float s = sec ? 1.0f : QSCALE;
#pragma unroll
        for (int mt = 0; mt < 4; mt++) {
            int tok = tokb + wm * 64 + mt * 16 + (lane >> 2);
#pragma unroll
            for (int nt = 0; nt < 4; nt++) {
                int col = cb * 128 + wn * 32 + nt * 8 + (lane & 3) * 2;
                int h = col >> 6, d = col & 63;
                size_t o0 = (((size_t)(b * HEADS + h)) * NTOK + tok) * DHEAD + d;
                *(uint32_t*)(oq + o0)             = pack2h(acc[mt][nt][0] * s, acc[mt][nt][1] * s);
                *(uint32_t*)(oq + o0 + 8 * DHEAD) = pack2h(acc[mt][nt][2] * s, acc[mt][nt][3] * s);
            }
        }
    } else {
        __syncthreads();
        __half* sh = (__half*)smem;          // [128][136]
#pragma unroll
        for (int mt = 0; mt < 4; mt++) {
            int r = wm * 64 + mt * 16 + (lane >> 2);
#pragma unroll
            for (int nt = 0; nt < 4; nt++) {
                int c = wn * 32 + nt * 8 + (lane & 3) * 2;
#pragma unroll
                for (int half_i = 0; half_i < 2; half_i++) {
                    int rr = r + half_i * 8;
                    sh[c * 136 + rr]       = __float2half_rn(acc[mt][nt][2 * half_i + 0]);
                    sh[(c + 1) * 136 + rr] = __float2half_rn(acc[mt][nt][2 * half_i + 1]);
                }
            }
        }
        __syncthreads();
        {
            int dl = tid >> 1, seg = (tid & 1) * 64;
            int h = cb * 2 + (dl >> 6), d = dl & 63;
            size_t o = (((size_t)(b * HEADS + h)) * DHEAD + d) * NTOK + tokb + seg;
#pragma unroll
            for (int j = 0; j < 8; j++)
                *(uint4*)(g_vT + o + j * 8) = *(uint4*)(sh + dl * 136 + seg + j * 8);
        }
    }
}

// ---------------------------------------------------------------------------
// Output-projection GEMM: att (single fp16) @ woutT + b_out -> fp32 out
// ---------------------------------------------------------------------------
__global__ __launch_bounds__(256, 2)
void gemm_out(float* __restrict__ C, const float* __restrict__ bias) {
    extern __shared__ char smem[];
    const int tid = threadIdx.x, wid = tid >> 5, lane = tid & 31;
    const int wm = wid >> 2, wn = wid & 3;
    const int bm = blockIdx.y * 128, bn = blockIdx.x * 128;
    const uint32_t sb = smem_u32(smem);

    constexpr int K = 512;
    float acc[4][4][4] = {};
    gemm_mainloop1(g_att + (size_t)bm * K, g_woutT + (size_t)bn * K,
                   sb, tid, wm, wn, lane, acc);

#pragma unroll
    for (int mt = 0; mt < 4; mt++) {
        int row0 = bm + wm * 64 + mt * 16 + (lane >> 2);
#pragma unroll
        for (int nt = 0; nt < 4; nt++) {
            int col = bn + wn * 32 + nt * 8 + (lane & 3) * 2;
            float b0 = bias[col], b1 = bias[col + 1];
            float2 v0 = make_float2(acc[mt][nt][0] + b0, acc[mt][nt][1] + b1);
            float2 v1 = make_float2(acc[mt][nt][2] + b0, acc[mt][nt][3] + b1);
            *(float2*)&C[(size_t)row0 * INNER + col]       = v0;
            *(float2*)&C[(size_t)(row0 + 8) * INNER + col] = v1;
        }
    }
}

// ---------------------------------------------------------------------------
// Flash attention, all-single fp16, exp2-domain softmax.
// 128 threads / 64 Q-rows, forced 3 CTAs/SM. SMEM 72KB.
// ---------------------------------------------------------------------------
#define ASMEM_Q  0
#define ASMEM_K  8192
#define ASMEM_V  40960
#define ASMEM_BYTES 73728

__global__ __launch_bounds__(128, 3)
void attn_mma() {
    extern __shared__ char smem[];
    const int tid = threadIdx.x, wid = tid >> 5, lane = tid & 31;
    const int qt = blockIdx.x, h = blockIdx.y, b = blockIdx.z;
    const int bh = b * HEADS + h;
    const uint32_t sb = smem_u32(smem);

    const __half* Q_g = g_q  + ((size_t)bh * NTOK + qt * 64) * DHEAD;
    const __half* K_g = g_k  + (size_t)bh * NTOK * DHEAD;
    const __half* V_g = g_vT + (size_t)bh * DHEAD * NTOK;

#pragma unroll
    for (int i = 0; i < 4; i++) {
        int cid = tid + 128 * i;
        int r = cid >> 3, c = cid & 7;
        cp16(sb + ASMEM_Q + r * 128 + ((c ^ (r & 7)) << 4),
             Q_g + (size_t)r * DHEAD + c * 8);
    }
    CP_COMMIT();

    auto issueKV = [&](int t) {
        const int s = t & 1;
        uint32_t kbase = sb + ASMEM_K + s * 16384;
#pragma unroll
        for (int i = 0; i < 8; i++) {
            int cid = tid + 128 * i;
            int r = cid >> 3, c = cid & 7;
            cp16(kbase + r * 128 + ((c ^ (r & 7)) << 4),
                 K_g + ((size_t)(t * 128 + r)) * DHEAD + c * 8);
        }
        uint32_t vbase = sb + ASMEM_V + s * 16384;
#pragma unroll
        for (int i = 0; i < 8; i++) {
            int cid = tid + 128 * i;
            int d = cid >> 4, c = cid & 15;
            cp16(vbase + d * 256 + ((c ^ (d & 7)) << 4),
                 V_g + (size_t)d * NTOK + t * 128 + c * 8);
        }
        CP_COMMIT();
    };
    issueKV(0);
    CP_WAIT0();
    __syncthreads();

    uint32_t aQ[4][4];
#pragma unroll
    for (int ks = 0; ks < 4; ks++) {
        int row = wid * 16 + (lane & 15);
        int c = 2 * ks + (lane >> 4);
        LDSM4(aQ[ks][0], aQ[ks][1], aQ[ks][2], aQ[ks][3],
              sb + ASMEM_Q + row * 128 + ((c ^ (row & 7)) << 4));
    }

    float O[8][4] = {};
    float l0 = 0.f, l1 = 0.f;
    const __half* bias_row0 =
        g_biasb + (size_t)h * NTOK * NTOK + (size_t)(qt * 64 + wid * 16 + (lane >> 2)) * NTOK;

    for (int t = 0; t < NTOK / 128; t++) {
        if (t > 0) { CP_WAIT0(); __syncthreads(); }
        if (t + 1 < NTOK / 128) issueKV(t + 1);

        const uint32_t kb = sb + ASMEM_K + (t & 1) * 16384;
        const uint32_t vb = sb + ASMEM_V + (t & 1) * 16384;

        // ---- S2 = (Q*log2e*0.125) K^T (single pass, log2-domain logits) ----
        float sc[16][4];
#pragma unroll
        for (int nt = 0; nt < 16; nt++) { sc[nt][0]=0.f; sc[nt][1]=0.f; sc[nt][2]=0.f; sc[nt][3]=0.f; }
#pragma unroll
        for (int ks = 0; ks < 4; ks++) {
#pragma unroll
            for (int np = 0; np < 8; np++) {
                int rowk = np * 16 + (lane & 7) + ((lane >> 4) << 3);
                int c = 2 * ks + ((lane >> 3) & 1);
                uint32_t kf[4];
                LDSM4(kf[0], kf[1], kf[2], kf[3],
                      kb + rowk * 128 + ((c ^ (rowk & 7)) << 4));
                uint32_t b0[2] = {kf[0], kf[1]}, b1[2] = {kf[2], kf[3]};
                MMA16816(sc[2*np],   aQ[ks], b0);
                MMA16816(sc[2*np+1], aQ[ks], b1);
            }
        }

        // ---- P = 2^(S2 + bias2 - OFF); accumulate row sums ----
        {
            const __half* bp0 = bias_row0 + t * 128 + 2 * (lane & 3);
            const __half* bp1 = bp0 + 8 * NTOK;
#pragma unroll
            for (int nt = 0; nt < 16; nt++) {
                uint32_t u0 = *(const uint32_t*)(bp0 + nt * 8);
                uint32_t u1 = *(const uint32_t*)(bp1 + nt * 8);
                float2 f0 = __half22float2(*reinterpret_cast<__half2*>(&u0));
                float2 f1 = __half22float2(*reinterpret_cast<__half2*>(&u1));
                sc[nt][0] = ex2(sc[nt][0] + f0.x - EXP2_OFF); l0 += sc[nt][0];
                sc[nt][1] = ex2(sc[nt][1] + f0.y - EXP2_OFF); l0 += sc[nt][1];
                sc[nt][2] = ex2(sc[nt][2] + f1.x - EXP2_OFF); l1 += sc[nt][2];
                sc[nt][3] = ex2(sc[nt][3] + f1.y - EXP2_OFF); l1 += sc[nt][3];
            }
        }

        // ---- O += P @ V (single fp16 P) ----
#pragma unroll
        for (int j = 0; j < 8; j++) {
            uint32_t aP[4];
            aP[0] = pack2h(sc[2*j][0],   sc[2*j][1]);
            aP[1] = pack2h(sc[2*j][2],   sc[2*j][3]);
            aP[2] = pack2h(sc[2*j+1][0], sc[2*j+1][1]);
            aP[3] = pack2h(sc[2*j+1][2], sc[2*j+1][3]);
#pragma unroll
            for (int np = 0; np < 4; np++) {
                int rowd = np * 16 + (lane & 7) + ((lane >> 4) << 3);
                int c = 2 * j + ((lane >> 3) & 1);
                uint32_t vf[4];
                LDSM4(vf[0], vf[1], vf[2], vf[3],
                      vb + rowd * 256 + ((c ^ (rowd & 7)) << 4));
                uint32_t b0[2] = {vf[0], vf[1]}, b1[2] = {vf[2], vf[3]};
                MMA16816(O[2*np],   aP, b0);
                MMA16816(O[2*np+1], aP, b1);
            }
        }
    }

    // ---- single end-of-row reduction + normalize + single-fp16 store ----
    l0 += __shfl_xor_sync(0xffffffffu, l0, 1);
    l0 += __shfl_xor_sync(0xffffffffu, l0, 2);
    l1 += __shfl_xor_sync(0xffffffffu, l1, 1);
    l1 += __shfl_xor_sync(0xffffffffu, l1, 2);
    float i0 = 1.f / l0, i1 = 1.f / l1;
    size_t r0 = (size_t)b * NTOK + qt * 64 + wid * 16 + (lane >> 2);
    int colo = h * DHEAD + 2 * (lane & 3);
#pragma unroll
    for (int dt = 0; dt < 8; dt++) {
        *(uint32_t*)(g_att + r0 * INNER + colo + dt * 8) =
            pack2h(O[dt][0] * i0, O[dt][1] * i0);
        *(uint32_t*)(g_att + (r0 + 8) * INNER + colo + dt * 8) =
            pack2h(O[dt][2] * i1, O[dt][3] * i1);
    }
}

// ---------------------------------------------------------------------------
extern "C" void kernel_launch(void* const* d_in, const int* in_sizes, int n_in,
                              void* d_out, int out_size) {
    const float* x          = (const float*)d_in[0];
    const float* w_qkv      = (const float*)d_in[1];
    const float* w_out      = (const float*)d_in[2];
    const float* b_out      = (const float*)d_in[3];
    const float* bias_table = (const float*)d_in[4];
    const int*   rel_index  = (const int*)  d_in[5];
    float* out = (float*)d_out;

    __half *xh, *xl, *wq, *wo;
    cudaGetSymbolAddress((void**)&xh, g_x_hi);
    cudaGetSymbolAddress((void**)&xl, g_x_lo);
    cudaGetSymbolAddress((void**)&wq, g_wqkvT);
    cudaGetSymbolAddress((void**)&wo, g_woutT);

    cudaFuncSetAttribute(gemm_qkv, cudaFuncAttributeMaxDynamicSharedMemorySize, GSMEM2_BYTES);
    cudaFuncSetAttribute(gemm_out, cudaFuncAttributeMaxDynamicSharedMemorySize, GSMEM1_BYTES);
    cudaFuncSetAttribute(attn_mma, cudaFuncAttributeMaxDynamicSharedMemorySize, ASMEM_BYTES);

    // 1) prep
    bias_kernel<<<(NTOK * NTOK + 255) / 256, 256>>>(bias_table, rel_index);
    {
        size_t n4 = (size_t)MROWS * INNER / 4;
        split_kernel<<<(unsigned)((n4 + 255) / 256), 256>>>(x, xh, xl, n4);
        splitTh_kernel<<<(INNER * QKV3 + 255) / 256, 256>>>(w_qkv, wq, INNER, QKV3);
        splitTh_kernel<<<(INNER * INNER + 255) / 256, 256>>>(w_out, wo, INNER, INNER);
    }

    // 2) QKV GEMM (section-wise precision) with fused repack epilogue
    gemm_qkv<<<dim3(QKV3 / 128, MROWS / 128), 256, GSMEM2_BYTES>>>();

    // 3) flash attention (64-row CTAs, 3/SM, exp2 softmax) -> g_att
    attn_mma<<<dim3(NTOK / 64, HEADS, BATCH), 128, ASMEM_BYTES>>>();

    // 4) out = att @ w_out + b_out
    gemm_out<<<dim3(INNER / 128, MROWS / 128), 256, GSMEM1_BYTES>>>(out, b_out);
}

// round 16
// speedup vs baseline: 1.0676x; 1.0676x over previous
#include <cuda_runtime.h>
#include <cuda_fp16.h>
#include <cstdint>
#include <cstddef>

#define NTOK   1024
#define BATCH  32
#define HEADS  8
#define DHEAD  64
#define INNER  512
#define QKV3   (3*INNER)
#define MROWS  (BATCH*NTOK)
#define BK     32

#define LOG2E  1.44269504f
#define QSCALE (0.125f * LOG2E)
#define EXP2_OFF 5.7707801f    // 4 * log2(e): P = 2^(S2+bias2-OFF) = e^(S+bias-4)

// ---------------- scratch (static device globals; no allocation allowed) ----
__device__ __half g_biasb[(size_t)HEADS*NTOK*NTOK];   // bias * log2e (fp16)

__device__ __half g_x_hi [(size_t)MROWS*INNER];       // x 2-term (A-side of qkv)
__device__ __half g_x_lo [(size_t)MROWS*INNER];
__device__ __half g_att  [(size_t)MROWS*INNER];       // attention out, single fp16
__device__ __half g_wqkvT[(size_t)QKV3*INNER];        // single fp16 (B-side)
__device__ __half g_woutT[(size_t)INNER*INNER];       // single fp16 (B-side)

// attention operands (all single fp16): Q,K [b,h,n,64]; V transposed [b,h,64,n]
__device__ __half g_q [(size_t)BATCH*HEADS*NTOK*DHEAD];  // Q pre-scaled by 0.125*log2e
__device__ __half g_k [(size_t)BATCH*HEADS*NTOK*DHEAD];
__device__ __half g_vT[(size_t)BATCH*HEADS*DHEAD*NTOK];

// ---------------- PTX helpers (base sm_103-safe) ----------------------------
__device__ __forceinline__ uint32_t smem_u32(const void* p) {
    uint32_t a;
    asm("{ .reg .u64 t; cvta.to.shared.u64 t, %1; cvt.u32.u64 %0, t; }"
        : "=r"(a) : "l"(p));
    return a;
}
__device__ __forceinline__ void cp16(uint32_t dst, const void* src) {
    asm volatile("cp.async.cg.shared.global [%0], [%1], 16;"
                 :: "r"(dst), "l"(src) : "memory");
}
#define CP_COMMIT() asm volatile("cp.async.commit_group;" ::: "memory")
#define CP_WAIT1()  asm volatile("cp.async.wait_group 1;" ::: "memory")
#define CP_WAIT0()  asm volatile("cp.async.wait_group 0;" ::: "memory")

#define LDSM4(r0, r1, r2, r3, addr)                                            \
    asm volatile("ldmatrix.sync.aligned.m8n8.x4.shared.b16 {%0,%1,%2,%3}, [%4];" \
                 : "=r"(r0), "=r"(r1), "=r"(r2), "=r"(r3) : "r"(addr))

#define MMA16816(d, a, b)                                                      \
    asm volatile("mma.sync.aligned.m16n8k16.row.col.f32.f16.f16.f32 "          \
                 "{%0,%1,%2,%3}, {%4,%5,%6,%7}, {%8,%9}, {%0,%1,%2,%3};"       \
                 : "+f"((d)[0]), "+f"((d)[1]), "+f"((d)[2]), "+f"((d)[3])      \
                 : "r"((a)[0]), "r"((a)[1]), "r"((a)[2]), "r"((a)[3]),         \
                   "r"((b)[0]), "r"((b)[1]))

__device__ __forceinline__ float ex2(float x) {
    float r;
    asm("ex2.approx.f32 %0, %1;" : "=f"(r) : "f"(x));
    return r;
}

__device__ __forceinline__ void split2h(float a, float b, uint32_t& hi, uint32_t& lo) {
    __half ha = __float2half_rn(a), hb = __float2half_rn(b);
    float ra = a - __half2float(ha), rb = b - __half2float(hb);
    __half la = __float2half_rn(ra), lb = __float2half_rn(rb);
    hi = ((uint32_t)__half_as_ushort(hb) << 16) | __half_as_ushort(ha);
    lo = ((uint32_t)__half_as_ushort(lb) << 16) | __half_as_ushort(la);
}
__device__ __forceinline__ uint32_t pack2h(float a, float b) {
    __half2 h = __float22half2_rn(make_float2(a, b));
    return *(uint32_t*)&h;
}

// ---------------------------------------------------------------------------
// bias (fp16), pre-scaled by log2(e) for the exp2-domain softmax
// ---------------------------------------------------------------------------
__global__ void bias_kernel(const float* __restrict__ bias_table,
                            const int*   __restrict__ rel_index) {
    int idx = blockIdx.x * blockDim.x + threadIdx.x;
    if (idx >= NTOK * NTOK) return;
    int r = rel_index[idx];
#pragma unroll
    for (int h = 0; h < HEADS; h++)
        g_biasb[(size_t)h * NTOK * NTOK + idx] =
            __float2half_rn(bias_table[r * HEADS + h] * LOG2E);
}

// ---------------------------------------------------------------------------
// split fp32 -> (hi, lo) fp16, same layout.
// ---------------------------------------------------------------------------
__global__ void split_kernel(const float* __restrict__ in,
                             __half* __restrict__ hi,
                             __half* __restrict__ lo, size_t n4) {
    size_t i = (size_t)blockIdx.x * blockDim.x + threadIdx.x;
    if (i >= n4) return;
    float4 v = ((const float4*)in)[i];
    uint32_t hp[2], lp[2];
    split2h(v.x, v.y, hp[0], lp[0]);
    split2h(v.z, v.w, hp[1], lp[1]);
    ((uint2*)hi)[i] = make_uint2(hp[0], hp[1]);
    ((uint2*)lo)[i] = make_uint2(lp[0], lp[1]);
}

// transpose weights: in [K,N] fp32 -> single fp16 [N,K]
__global__ void splitTh_kernel(const float* __restrict__ in,
                               __half* __restrict__ hT, int K, int N) {
    int idx = blockIdx.x * blockDim.x + threadIdx.x;
    if (idx >= K * N) return;
    int n = idx / K, k = idx - n * K;
    hT[idx] = __float2half_rn(in[(size_t)k * N + n]);
}

// ---------------------------------------------------------------------------
// GEMM mainloop, A 2-term: (Ahi+Alo) @ B^T, K=512, 3-stage cp.async.
// ---------------------------------------------------------------------------
#define STAGE2_BYTES 24576
#define GSMEM2_BYTES (3 * STAGE2_BYTES)

__device__ __forceinline__ void gemm_mainloop2(
    const __half* srcAh, const __half* srcAl, const __half* srcB,
    uint32_t sb, int tid, int wm, int wn, int lane, float acc[4][4][4]) {
    constexpr int K = 512;

    auto issue = [&](int stage, int c) {
        const uint32_t d0 = sb + stage * STAGE2_BYTES;
        const int k0 = c * BK;
        const __half* srcs[3] = {srcAh, srcAl, srcB};
#pragma unroll
        for (int o = 0; o < 3; o++) {
#pragma unroll
            for (int i = 0; i < 2; i++) {
                int cid = tid + 256 * i;
                int row = cid >> 2, ch = cid & 3;
                int cc = ch ^ ((row >> 1) & 3);
                cp16(d0 + o * 8192 + row * 64 + cc * 16,
                     srcs[o] + (size_t)row * K + k0 + ch * 8);
            }
        }
    };

    issue(0, 0); CP_COMMIT();
    issue(1, 1); CP_COMMIT();

    for (int c = 0; c < K / BK; c++) {
        const int s = c % 3;
        CP_WAIT1();
        __syncthreads();
        if (c + 2 < K / BK) issue((c + 2) % 3, c + 2);
        CP_COMMIT();

        const uint32_t stg = sb + s * STAGE2_BYTES;
#pragma unroll
        for (int ks = 0; ks < 2; ks++) {
            uint32_t aH[4][4], aL[4][4], bF[4][2];
#pragma unroll
            for (int mt = 0; mt < 4; mt++) {
                int row = wm * 64 + mt * 16 + (lane & 15);
                int ch = 2 * ks + (lane >> 4);
                int cc = ch ^ ((row >> 1) & 3);
                uint32_t ad = stg + row * 64 + cc * 16;
                LDSM4(aH[mt][0], aH[mt][1], aH[mt][2], aH[mt][3], ad);
                LDSM4(aL[mt][0], aL[mt][1], aL[mt][2], aL[mt][3], ad + 8192);
            }
#pragma unroll
            for (int np = 0; np < 2; np++) {
                int rown = wn * 32 + np * 16 + (lane & 7) + ((lane >> 4) << 3);
                int ch = 2 * ks + ((lane >> 3) & 1);
                int cc = ch ^ ((rown >> 1) & 3);
                uint32_t bd = stg + 16384 + rown * 64 + cc * 16;
                LDSM4(bF[2*np][0], bF[2*np][1], bF[2*np+1][0], bF[2*np+1][1], bd);
            }
#pragma unroll
            for (int mt = 0; mt < 4; mt++)
#pragma unroll
                for (int nt = 0; nt < 4; nt++) {
                    MMA16816(acc[mt][nt], aH[mt], bF[nt]);
                    MMA16816(acc[mt][nt], aL[mt], bF[nt]);
                }
        }
    }
}

// ---------------------------------------------------------------------------
// GEMM mainloop, A single-term: A @ B^T, K=512, 3-stage cp.async.
// ---------------------------------------------------------------------------
#define STAGE1_BYTES 16384
#define GSMEM1_BYTES (3 * STAGE1_BYTES)

__device__ __forceinline__ void gemm_mainloop1(
    const __half* srcA, const __half* srcB,
    uint32_t sb, int tid, int wm, int wn, int lane, float acc[4][4][4]) {
    constexpr int K = 512;

    auto issue = [&](int stage, int c) {
        const uint32_t d0 = sb + stage * STAGE1_BYTES;
        const int k0 = c * BK;
        const __half* srcs[2] = {srcA, srcB};
#pragma unroll
        for (int o = 0; o < 2; o++) {
#pragma unroll
            for (int i = 0; i < 2; i++) {
                int cid = tid + 256 * i;
                int row = cid >> 2, ch = cid & 3;
                int cc = ch ^ ((row >> 1) & 3);
                cp16(d0 + o * 8192 + row * 64 + cc * 16,
                     srcs[o] + (size_t)row * K + k0 + ch * 8);
            }
        }
    };

    issue(0, 0); CP_COMMIT();
    issue(1, 1); CP_COMMIT();

    for (int c = 0; c < K / BK; c++) {
        const int s = c % 3;
        CP_WAIT1();
        __syncthreads();
        if (c + 2 < K / BK) issue((c + 2) % 3, c + 2);
        CP_COMMIT();

        const uint32_t stg = sb + s * STAGE1_BYTES;
#pragma unroll
        for (int ks = 0; ks < 2; ks++) {
            uint32_t aF[4][4], bF[4][2];
#pragma unroll
            for (int mt = 0; mt < 4; mt++) {
                int row = wm * 64 + mt * 16 + (lane & 15);
                int ch = 2 * ks + (lane >> 4);
                int cc = ch ^ ((row >> 1) & 3);
                LDSM4(aF[mt][0], aF[mt][1], aF[mt][2], aF[mt][3],
                      stg + row * 64 + cc * 16);
            }
#pragma unroll
            for (int np = 0; np < 2; np++) {
                int rown = wn * 32 + np * 16 + (lane & 7) + ((lane >> 4) << 3);
                int ch = 2 * ks + ((lane >> 3) & 1);
                int cc = ch ^ ((rown >> 1) & 3);
                uint32_t bd = stg + 8192 + rown * 64 + cc * 16;
                LDSM4(bF[2*np][0], bF[2*np][1], bF[2*np+1][0], bF[2*np+1][1], bd);
            }
#pragma unroll
            for (int mt = 0; mt < 4; mt++)
#pragma unroll
                for (int nt = 0; nt < 4; nt++)
                    MMA16816(acc[mt][nt], aF[mt], bF[nt]);
        }
    }
}

// ---------------------------------------------------------------------------
// QKV GEMM with fused repack epilogue + section-wise precision:
//   Q (sec 0): x 2-term mainloop, scale 0.125*log2e -> g_q [bh,tok,64]
//   K (sec 1): x single-term mainloop               -> g_k [bh,tok,64]
//   V (sec 2): x single-term mainloop + transpose   -> g_vT [bh,d,tok]
// ---------------------------------------------------------------------------
__global__ __launch_bounds__(256, 2)
void gemm_qkv() {
    extern __shared__ char smem[];
    const int tid = threadIdx.x, wid = tid >> 5, lane = tid & 31;
    const int wm = wid >> 2, wn = wid & 3;
    const int bm = blockIdx.y * 128;
    const int sec = blockIdx.x >> 2;        // 0=Q 1=K 2=V
    const int cb  = blockIdx.x & 3;
    const uint32_t sb = smem_u32(smem);

    constexpr int K = 512;
    float acc[4][4][4] = {};
    if (sec == 0) {
        gemm_mainloop2(g_x_hi + (size_t)bm * K, g_x_lo + (size_t)bm * K,
                       g_wqkvT + (size_t)(cb * 128) * K,
                       sb, tid, wm, wn, lane, acc);
    } else {
        gemm_mainloop1(g_x_hi + (size_t)bm * K,
                       g_wqkvT + (size_t)(sec * 512 + cb * 128) * K,
                       sb, tid, wm, wn, lane, acc);
    }

    const int b = bm >> 10, tokb = bm & 1023;

    if (sec < 2) {
        __half* oq = sec ? g_k : g_q;
        const float s = sec ? 1.0f : QSCALE;
#pragma unroll
        for (int mt = 0; mt < 4; mt++) {
            int tok = tokb + wm * 64 + mt * 16 + (lane >> 2);
#pragma unroll
            for (int nt = 0; nt < 4; nt++) {
                int col = cb * 128 + wn * 32 + nt * 8 + (lane & 3) * 2;
                int h = col >> 6, d = col & 63;
                size_t o0 = (((size_t)(b * HEADS + h)) * NTOK + tok) * DHEAD + d;
                *(uint32_t*)(oq + o0)             = pack2h(acc[mt][nt][0] * s, acc[mt][nt][1] * s);
                *(uint32_t*)(oq + o0 + 8 * DHEAD) = pack2h(acc[mt][nt][2] * s, acc[mt][nt][3] * s);
            }
        }
    } else {
        __syncthreads();
        __half* sh = (__half*)smem;          // [128][136]
#pragma unroll
        for (int mt = 0; mt < 4; mt++) {
            int r = wm * 64 + mt * 16 + (lane >> 2);
#pragma unroll
            for (int nt = 0; nt < 4; nt++) {
                int c = wn * 32 + nt * 8 + (lane & 3) * 2;
#pragma unroll
                for (int half_i = 0; half_i < 2; half_i++) {
                    int rr = r + half_i * 8;
                    sh[c * 136 + rr]       = __float2half_rn(acc[mt][nt][2 * half_i + 0]);
                    sh[(c + 1) * 136 + rr] = __float2half_rn(acc[mt][nt][2 * half_i + 1]);
                }
            }
        }
        __syncthreads();
        {
            int dl = tid >> 1, seg = (tid & 1) * 64;
            int h = cb * 2 + (dl >> 6), d = dl & 63;
            size_t o = (((size_t)(b * HEADS + h)) * DHEAD + d) * NTOK + tokb + seg;
#pragma unroll
            for (int j = 0; j < 8; j++)
                *(uint4*)(g_vT + o + j * 8) = *(uint4*)(sh + dl * 136 + seg + j * 8);
        }
    }
}

// ---------------------------------------------------------------------------
// Output-projection GEMM: att (single fp16) @ woutT + b_out -> fp32 out
// ---------------------------------------------------------------------------
__global__ __launch_bounds__(256, 2)
void gemm_out(float* __restrict__ C, const float* __restrict__ bias) {
    extern __shared__ char smem[];
    const int tid = threadIdx.x, wid = tid >> 5, lane = tid & 31;
    const int wm = wid >> 2, wn = wid & 3;
    const int bm = blockIdx.y * 128, bn = blockIdx.x * 128;
    const uint32_t sb = smem_u32(smem);

    constexpr int K = 512;
    float acc[4][4][4] = {};
    gemm_mainloop1(g_att + (size_t)bm * K, g_woutT + (size_t)bn * K,
                   sb, tid, wm, wn, lane, acc);

#pragma unroll
    for (int mt = 0; mt < 4; mt++) {
        int row0 = bm + wm * 64 + mt * 16 + (lane >> 2);
#pragma unroll
        for (int nt = 0; nt < 4; nt++) {
            int col = bn + wn * 32 + nt * 8 + (lane & 3) * 2;
            float b0 = bias[col], b1 = bias[col + 1];
            float2 v0 = make_float2(acc[mt][nt][0] + b0, acc[mt][nt][1] + b1);
            float2 v1 = make_float2(acc[mt][nt][2] + b0, acc[mt][nt][3] + b1);
            *(float2*)&C[(size_t)row0 * INNER + col]       = v0;
            *(float2*)&C[(size_t)(row0 + 8) * INNER + col] = v1;
        }
    }
}

// ---------------------------------------------------------------------------
// Flash attention, all-single fp16, exp2-domain softmax.
// 128 threads / 64 Q-rows per CTA, natural register allocation (no forced
// occupancy cap — R15 showed the cap's spills cost more than the 3rd CTA).
// SMEM: Q 8KB | K 2-stage 32KB | V 2-stage 32KB = 72KB.
// ---------------------------------------------------------------------------
#define ASMEM_Q  0
#define ASMEM_K  8192
#define ASMEM_V  40960
#define ASMEM_BYTES 73728

__global__ __launch_bounds__(128)
void attn_mma() {
    extern __shared__ char smem[];
    const int tid = threadIdx.x, wid = tid >> 5, lane = tid & 31;
    const int qt = blockIdx.x, h = blockIdx.y, b = blockIdx.z;
    const int bh = b * HEADS + h;
    const uint32_t sb = smem_u32(smem);

    const __half* Q_g = g_q  + ((size_t)bh * NTOK + qt * 64) * DHEAD;
    const __half* K_g = g_k  + (size_t)bh * NTOK * DHEAD;
    const __half* V_g = g_vT + (size_t)bh * DHEAD * NTOK;

#pragma unroll
    for (int i = 0; i < 4; i++) {
        int cid = tid + 128 * i;
        int r = cid >> 3, c = cid & 7;
        cp16(sb + ASMEM_Q + r * 128 + ((c ^ (r & 7)) << 4),
             Q_g + (size_t)r * DHEAD + c * 8);
    }
    CP_COMMIT();

    auto issueKV = [&](int t) {
        const int s = t & 1;
        uint32_t kbase = sb + ASMEM_K + s * 16384;
#pragma unroll
        for (int i = 0; i < 8; i++) {
            int cid = tid + 128 * i;
            int r = cid >> 3, c = cid & 7;
            cp16(kbase + r * 128 + ((c ^ (r & 7)) << 4),
                 K_g + ((size_t)(t * 128 + r)) * DHEAD + c * 8);
        }
        uint32_t vbase = sb + ASMEM_V + s * 16384;
#pragma unroll
        for (int i = 0; i < 8; i++) {
            int cid = tid + 128 * i;
            int d = cid >> 4, c = cid & 15;
            cp16(vbase + d * 256 + ((c ^ (d & 7)) << 4),
                 V_g + (size_t)d * NTOK + t * 128 + c * 8);
        }
        CP_COMMIT();
    };
    issueKV(0);
    CP_WAIT0();
    __syncthreads();

    uint32_t aQ[4][4];
#pragma unroll
    for (int ks = 0; ks < 4; ks++) {
        int row = wid * 16 + (lane & 15);
        int c = 2 * ks + (lane >> 4);
        LDSM4(aQ[ks][0], aQ[ks][1], aQ[ks][2], aQ[ks][3],
              sb + ASMEM_Q + row * 128 + ((c ^ (row & 7)) << 4));
    }

    float O[8][4] = {};
    float l0 = 0.f, l1 = 0.f;
    const __half* bias_row0 =
        g_biasb + (size_t)h * NTOK * NTOK + (size_t)(qt * 64 + wid * 16 + (lane >> 2)) * NTOK;

    for (int t = 0; t < NTOK / 128; t++) {
        if (t > 0) { CP_WAIT0(); __syncthreads(); }
        if (t + 1 < NTOK / 128) issueKV(t + 1);

        const uint32_t kb = sb + ASMEM_K + (t & 1) * 16384;
        const uint32_t vb = sb + ASMEM_V + (t & 1) * 16384;

        // ---- S2 = (Q*log2e*0.125) K^T (single pass, log2-domain logits) ----
        float sc[16][4];
#pragma unroll
        for (int nt = 0; nt < 16; nt++) { sc[nt][0]=0.f; sc[nt][1]=0.f; sc[nt][2]=0.f; sc[nt][3]=0.f; }
#pragma unroll
        for (int ks = 0; ks < 4; ks++) {
#pragma unroll
            for (int np = 0; np < 8; np++) {
                int rowk = np * 16 + (lane & 7) + ((lane >> 4) << 3);
                int c = 2 * ks + ((lane >> 3) & 1);
                uint32_t kf[4];
                LDSM4(kf[0], kf[1], kf[2], kf[3],
                      kb + rowk * 128 + ((c ^ (rowk & 7)) << 4));
                uint32_t b0[2] = {kf[0], kf[1]}, b1[2] = {kf[2], kf[3]};
                MMA16816(sc[2*np],   aQ[ks], b0);
                MMA16816(sc[2*np+1], aQ[ks], b1);
            }
        }

        // ---- P = 2^(S2 + bias2 - OFF); accumulate row sums ----
        {
            const __half* bp0 = bias_row0 + t * 128 + 2 * (lane & 3);
            const __half* bp1 = bp0 + 8 * NTOK;
#pragma unroll
            for (int nt = 0; nt < 16; nt++) {
                uint32_t u0 = *(const uint32_t*)(bp0 + nt * 8);
                uint32_t u1 = *(const uint32_t*)(bp1 + nt * 8);
                float2 f0 = __half22float2(*reinterpret_cast<__half2*>(&u0));
                float2 f1 = __half22float2(*reinterpret_cast<__half2*>(&u1));
                sc[nt][0] = ex2(sc[nt][0] + f0.x - EXP2_OFF); l0 += sc[nt][0];
                sc[nt][1] = ex2(sc[nt][1] + f0.y - EXP2_OFF); l0 += sc[nt][1];
                sc[nt][2] = ex2(sc[nt][2] + f1.x - EXP2_OFF); l1 += sc[nt][2];
                sc[nt][3] = ex2(sc[nt][3] + f1.y - EXP2_OFF); l1 += sc[nt][3];
            }
        }

        // ---- O += P @ V (single fp16 P) ----
#pragma unroll
        for (int j = 0; j < 8; j++) {
            uint32_t aP[4];
            aP[0] = pack2h(sc[2*j][0],   sc[2*j][1]);
            aP[1] = pack2h(sc[2*j][2],   sc[2*j][3]);
            aP[2] = pack2h(sc[2*j+1][0], sc[2*j+1][1]);
            aP[3] = pack2h(sc[2*j+1][2], sc[2*j+1][3]);
#pragma unroll
            for (int np = 0; np < 4; np++) {
                int rowd = np * 16 + (lane & 7) + ((lane >> 4) << 3);
                int c = 2 * j + ((lane >> 3) & 1);
                uint32_t vf[4];
                LDSM4(vf[0], vf[1], vf[2], vf[3],
                      vb + rowd * 256 + ((c ^ (rowd & 7)) << 4));
                uint32_t b0[2] = {vf[0], vf[1]}, b1[2] = {vf[2], vf[3]};
                MMA16816(O[2*np],   aP, b0);
                MMA16816(O[2*np+1], aP, b1);
            }
        }
    }

    // ---- single end-of-row reduction + normalize + single-fp16 store ----
    l0 += __shfl_xor_sync(0xffffffffu, l0, 1);
    l0 += __shfl_xor_sync(0xffffffffu, l0, 2);
    l1 += __shfl_xor_sync(0xffffffffu, l1, 1);
    l1 += __shfl_xor_sync(0xffffffffu, l1, 2);
    float i0 = 1.f / l0, i1 = 1.f / l1;
    size_t r0 = (size_t)b * NTOK + qt * 64 + wid * 16 + (lane >> 2);
    int colo = h * DHEAD + 2 * (lane & 3);
#pragma unroll
    for (int dt = 0; dt < 8; dt++) {
        *(uint32_t*)(g_att + r0 * INNER + colo + dt * 8) =
            pack2h(O[dt][0] * i0, O[dt][1] * i0);
        *(uint32_t*)(g_att + (r0 + 8) * INNER + colo + dt * 8) =
            pack2h(O[dt][2] * i1, O[dt][3] * i1);
    }
}

// ---------------------------------------------------------------------------
extern "C" void kernel_launch(void* const* d_in, const int* in_sizes, int n_in,
                              void* d_out, int out_size) {
    const float* x          = (const float*)d_in[0];
    const float* w_qkv      = (const float*)d_in[1];
    const float* w_out      = (const float*)d_in[2];
    const float* b_out      = (const float*)d_in[3];
    const float* bias_table = (const float*)d_in[4];
    const int*   rel_index  = (const int*)  d_in[5];
    float* out = (float*)d_out;

    __half *xh, *xl, *wq, *wo;
    cudaGetSymbolAddress((void**)&xh, g_x_hi);
    cudaGetSymbolAddress((void**)&xl, g_x_lo);
    cudaGetSymbolAddress((void**)&wq, g_wqkvT);
    cudaGetSymbolAddress((void**)&wo, g_woutT);

    cudaFuncSetAttribute(gemm_qkv, cudaFuncAttributeMaxDynamicSharedMemorySize, GSMEM2_BYTES);
    cudaFuncSetAttribute(gemm_out, cudaFuncAttributeMaxDynamicSharedMemorySize, GSMEM1_BYTES);
    cudaFuncSetAttribute(attn_mma, cudaFuncAttributeMaxDynamicSharedMemorySize, ASMEM_BYTES);

    // 1) prep
    bias_kernel<<<(NTOK * NTOK + 255) / 256, 256>>>(bias_table, rel_index);
    {
        size_t n4 = (size_t)MROWS * INNER / 4;
        split_kernel<<<(unsigned)((n4 + 255) / 256), 256>>>(x, xh, xl, n4);
        splitTh_kernel<<<(INNER * QKV3 + 255) / 256, 256>>>(w_qkv, wq, INNER, QKV3);
        splitTh_kernel<<<(INNER * INNER + 255) / 256, 256>>>(w_out, wo, INNER, INNER);
    }

    // 2) QKV GEMM (section-wise precision) with fused repack epilogue
    gemm_qkv<<<dim3(QKV3 / 128, MROWS / 128), 256, GSMEM2_BYTES>>>();

    // 3) flash attention (64-row CTAs, natural occupancy, exp2 softmax)
    attn_mma<<<dim3(NTOK / 64, HEADS, BATCH), 128, ASMEM_BYTES>>>();

    // 4) out = att @ w_out + b_out
    gemm_out<<<dim3(INNER / 128, MROWS / 128), 256, GSMEM1_BYTES>>>(out, b_out);
}